// round 8
// baseline (speedup 1.0000x reference)
#include <cuda_runtime.h>

#define N_NODES 100000
#define N_EDGES 3200000
#define IN_CH   64
#define OUT_C   25
#define W_ELEMS (2 * IN_CH * OUT_C)   // 3200
#define YPAD    32   // pad y rows to 32 floats = 128 B = one aligned L2 line

// Scratch: y_top at [n*YPAD], y_bot at [(N_NODES + n)*YPAD]. 25.6 MB static.
__device__ __align__(128) float g_y[2u * N_NODES * YPAD];

__device__ __forceinline__ float tanh_approx(float x) {
    float y;
    asm("tanh.approx.f32 %0, %1;" : "=f"(y) : "f"(x));
    return y;
}

// Deterministic buffer sniff: index data (int32, or int64 split into
// low/zero-high words) has EVERY 32-bit word < 0x20000 (indices < 100000).
// fp32 N(0,1) data fails this with probability ~0. Fixed addresses ->
// identical result in every block (deterministic, graph-safe).
__device__ __forceinline__ bool looks_like_indices(const void* p) {
    const unsigned* u = (const unsigned*)p;
    bool small = true;
#pragma unroll
    for (int i = 0; i < 64; ++i) small &= (__ldg(u + i) < 0x20000u);
    return small;
}

// ---------------------------------------------------------------------------
// Kernel 1: per-node precompute  y_top[n] = x[n] @ W[0:64],  y_bot[n] = x[n] @ W[64:128]
// One thread per node. W repacked into smem as [64][56]:
//   cols 0..27  = W[k][c]      (c<25, zero-padded)
//   cols 28..55 = W[64+k][c]   (c<25, zero-padded)
// pA/pB are the two 6.4M-element inputs (x and edge_index, order unknown).
// ---------------------------------------------------------------------------
__global__ void __launch_bounds__(128) precompute_kernel(const void* __restrict__ pA,
                                                         const void* __restrict__ pB,
                                                         const float* __restrict__ W) {
    const float* x = looks_like_indices(pA) ? (const float*)pB : (const float*)pA;

    __shared__ __align__(16) float ws[64 * 56];
    for (int i = threadIdx.x; i < 64 * 56; i += 128) {
        int k = i / 56, c = i % 56;
        float v = 0.0f;
        if (c < 28) {
            if (c < 25) v = W[k * 25 + c];
        } else {
            int cc = c - 28;
            if (cc < 25) v = W[(64 + k) * 25 + cc];
        }
        ws[i] = v;
    }
    __syncthreads();

    int n = blockIdx.x * 128 + threadIdx.x;
    if (n >= N_NODES) return;

    float4 accT[7], accB[7];
#pragma unroll
    for (int i = 0; i < 7; ++i) {
        accT[i] = make_float4(0.f, 0.f, 0.f, 0.f);
        accB[i] = make_float4(0.f, 0.f, 0.f, 0.f);
    }

    const float4* xr = (const float4*)(x + (size_t)n * IN_CH);
#pragma unroll 4
    for (int k4 = 0; k4 < 16; ++k4) {
        float4 xv = __ldg(xr + k4);
#pragma unroll
        for (int kk = 0; kk < 4; ++kk) {
            float xs = (kk == 0) ? xv.x : (kk == 1) ? xv.y : (kk == 2) ? xv.z : xv.w;
            const float4* wrow = (const float4*)(ws + (k4 * 4 + kk) * 56);
#pragma unroll
            for (int c = 0; c < 7; ++c) {
                float4 w = wrow[c];
                accT[c].x += xs * w.x;  accT[c].y += xs * w.y;
                accT[c].z += xs * w.z;  accT[c].w += xs * w.w;
            }
#pragma unroll
            for (int c = 0; c < 7; ++c) {
                float4 w = wrow[7 + c];
                accB[c].x += xs * w.x;  accB[c].y += xs * w.y;
                accB[c].z += xs * w.z;  accB[c].w += xs * w.w;
            }
        }
    }

    // Store to L2 (skip L1): consumed only by the next kernel via L2.
    float4* yt = (float4*)(g_y + (size_t)n * YPAD);
    float4* yb = (float4*)(g_y + (size_t)(N_NODES + n) * YPAD);
#pragma unroll
    for (int i = 0; i < 7; ++i) { __stcg(yt + i, accT[i]); __stcg(yb + i, accB[i]); }
}

// ---------------------------------------------------------------------------
// Kernel 2: edge pass. out[e] = tanh(y_top[row[e]] + y_bot[col[e]])
// 256 threads / 256 edges per block. 8 lanes cooperate per edge (float4 each)
// so each gather is exactly one 128B line / one L1tex wavefront. Index dtype
// (int64 vs int32) is sniffed: int64 data has all odd 32-bit words == 0.
// ---------------------------------------------------------------------------
__global__ void __launch_bounds__(256) edge_kernel(const void* __restrict__ pA,
                                                   const void* __restrict__ pB,
                                                   float* __restrict__ out) {
    __shared__ __align__(16) float so[256 * OUT_C];  // 25600 B

    const void* ei_raw = looks_like_indices(pA) ? pA : pB;
    const int*       ei32 = (const int*)ei_raw;
    const long long* ei64 = (const long long*)ei_raw;

    // dtype sniff: int64 indices -> every odd 32-bit word is zero.
    bool is64 = true;
#pragma unroll
    for (int i = 1; i < 64; i += 2) is64 &= (__ldg((const unsigned*)ei_raw + i) == 0u);

    const int tid  = threadIdx.x;
    const int warp = tid >> 5;
    const int lane = tid & 31;
    const int g    = lane >> 3;   // edge-within-group-of-4
    const int li   = lane & 7;    // float4 index within edge row
    const int tile = blockIdx.x * 256;

    const float* ytop = g_y;
    const float* ybot = g_y + (size_t)N_NODES * YPAD;

    // Front-batch all index loads: 16 independent loads in flight (MLP >> 4).
    long long r[8], c[8];
    if (is64) {
#pragma unroll
        for (int it = 0; it < 8; ++it) {
            int e = tile + warp * 32 + it * 4 + g;
            r[it] = __ldcs(ei64 + e);
            c[it] = __ldcs(ei64 + N_EDGES + e);
        }
    } else {
#pragma unroll
        for (int it = 0; it < 8; ++it) {
            int e = tile + warp * 32 + it * 4 + g;
            r[it] = (long long)__ldcs(ei32 + e);
            c[it] = (long long)__ldcs(ei32 + N_EDGES + e);
        }
    }

#pragma unroll
    for (int it = 0; it < 8; ++it) {
        int le = warp * 32 + it * 4 + g;      // local edge 0..255

        // Clamp: identity on valid input; turns any residual ABI surprise
        // into a wrong-answer (rel_err signal) instead of an illegal access.
        long long ri = min(max(r[it], 0LL), (long long)(N_NODES - 1));
        long long ci = min(max(c[it], 0LL), (long long)(N_NODES - 1));

        float4 a = __ldg((const float4*)(ytop + ri * YPAD) + li);
        float4 b = __ldg((const float4*)(ybot + ci * YPAD) + li);

        int base = le * OUT_C + li * 4;
        if (li < 6) {
            // smem addr = le*25 + li*4 + j : conflict-free across the warp
            so[base + 0] = tanh_approx(a.x + b.x);
            so[base + 1] = tanh_approx(a.y + b.y);
            so[base + 2] = tanh_approx(a.z + b.z);
            so[base + 3] = tanh_approx(a.w + b.w);
        } else if (li == 6) {
            so[base] = tanh_approx(a.x + b.x);  // element 24 only
        }
        // li == 7: load lands in the same 128B line (pad) — no extra traffic, no store
    }
    __syncthreads();

    // Coalesced streaming write: 256*25 = 6400 floats = 1600 float4 = 6*256 + 64
    const float4* so4 = (const float4*)so;
    float4* o4 = (float4*)(out + (size_t)tile * OUT_C);
#pragma unroll
    for (int i = 0; i < 6; ++i)
        __stcs(o4 + tid + i * 256, so4[tid + i * 256]);
    if (tid < 64)
        __stcs(o4 + tid + 1536, so4[tid + 1536]);
}

// ---------------------------------------------------------------------------
extern "C" void kernel_launch(void* const* d_in, const int* in_sizes, int n_in,
                              void* d_out, int out_size) {
    // W is the unique size-3200 input. x and edge_index have IDENTICAL element
    // counts (6.4M), so the remaining two are disambiguated on-device by a
    // deterministic content sniff (see looks_like_indices).
    int wi = 0;
    for (int i = 0; i < n_in; ++i)
        if (in_sizes[i] == W_ELEMS) wi = i;
    int ai = (wi == 0) ? 1 : 0;
    int bi = (wi == 2) ? 1 : 2;

    const void*  pA  = d_in[ai];
    const void*  pB  = d_in[bi];
    const float* W   = (const float*)d_in[wi];
    float*       out = (float*)d_out;

    precompute_kernel<<<(N_NODES + 127) / 128, 128>>>(pA, pB, W);
    edge_kernel<<<N_EDGES / 256, 256>>>(pA, pB, out);
}

// round 9
// speedup vs baseline: 1.0089x; 1.0089x over previous
#include <cuda_runtime.h>

#define N_NODES 100000
#define N_EDGES 3200000
#define IN_CH   64
#define OUT_C   25
#define W_ELEMS (2 * IN_CH * OUT_C)   // 3200
#define YPAD    32   // pad y rows to 32 floats = 128 B = one aligned L2 line

// Scratch: y_top at [n*YPAD], y_bot at [(N_NODES + n)*YPAD]. 25.6 MB static.
// Zero-initialized at load; floats 28..31 of each row stay 0 (read by li==7, discarded).
__device__ __align__(128) float g_y[2u * N_NODES * YPAD];

__device__ __forceinline__ float tanh_approx(float x) {
    float y;
    asm("tanh.approx.f32 %0, %1;" : "=f"(y) : "f"(x));
    return y;
}

// Deterministic buffer sniff: index data (int32, or int64 split into
// low/zero-high words) has EVERY 32-bit word < 0x20000 (indices < 100000).
// fp32 N(0,1) data fails this with probability ~0. Fixed addresses ->
// identical result in every block (deterministic, graph-safe).
__device__ __forceinline__ bool looks_like_indices(const void* p) {
    const unsigned* u = (const unsigned*)p;
    bool small = true;
#pragma unroll
    for (int i = 0; i < 64; ++i) small &= (__ldg(u + i) < 0x20000u);
    return small;
}

// Packed f32x2 FMA (sm_103a): d = a * b + d on two fp32 lanes in one instruction.
__device__ __forceinline__ void fma2(unsigned long long& d,
                                     unsigned long long a, unsigned long long b) {
    asm("fma.rn.f32x2 %0, %1, %2, %0;" : "+l"(d) : "l"(a), "l"(b));
}

// ---------------------------------------------------------------------------
// Kernel 1: per-node precompute  y_top[n] = x[n] @ W[0:64],  y_bot[n] = x[n] @ W[64:128]
// One thread per node, packed-f32x2 accumulation (halves fp32 instr count).
// W repacked into smem as [64][56]: cols 0..27 = W_top (25 + 3 zeros),
// cols 28..55 = W_bot (25 + 3 zeros).
// ---------------------------------------------------------------------------
__global__ void __launch_bounds__(128) precompute_kernel(const void* __restrict__ pA,
                                                         const void* __restrict__ pB,
                                                         const float* __restrict__ W) {
    const float* x = looks_like_indices(pA) ? (const float*)pB : (const float*)pA;

    __shared__ __align__(16) float ws[64 * 56];
    for (int i = threadIdx.x; i < 64 * 56; i += 128) {
        int k = i / 56, c = i % 56;
        float v = 0.0f;
        if (c < 28) {
            if (c < 25) v = W[k * 25 + c];
        } else {
            int cc = c - 28;
            if (cc < 25) v = W[(64 + k) * 25 + cc];
        }
        ws[i] = v;
    }
    __syncthreads();

    int n = blockIdx.x * 128 + threadIdx.x;
    if (n >= N_NODES) return;

    unsigned long long acc[28];   // 28 x f32x2 = 56 floats (28 top | 28 bottom)
#pragma unroll
    for (int i = 0; i < 28; ++i) acc[i] = 0ull;  // (0.0f, 0.0f)

    const float4* xr = (const float4*)(x + (size_t)n * IN_CH);
#pragma unroll 2
    for (int k4 = 0; k4 < 16; ++k4) {
        float4 xv = __ldg(xr + k4);
#pragma unroll
        for (int kk = 0; kk < 4; ++kk) {
            float xs = (kk == 0) ? xv.x : (kk == 1) ? xv.y : (kk == 2) ? xv.z : xv.w;
            unsigned long long x2;
            asm("mov.b64 %0, {%1, %1};" : "=l"(x2) : "f"(xs));
            const ulonglong2* wrow = (const ulonglong2*)(ws + (k4 * 4 + kk) * 56);
#pragma unroll
            for (int c = 0; c < 14; ++c) {
                ulonglong2 w = wrow[c];          // LDS.128 broadcast (2 f32x2 pairs)
                fma2(acc[2 * c],     x2, w.x);
                fma2(acc[2 * c + 1], x2, w.y);
            }
        }
    }

    // acc[0..13] = top 28 floats, acc[14..27] = bottom 28 floats.
    ulonglong2* yt = (ulonglong2*)(g_y + (size_t)n * YPAD);
    ulonglong2* yb = (ulonglong2*)(g_y + (size_t)(N_NODES + n) * YPAD);
#pragma unroll
    for (int i = 0; i < 7; ++i) {
        __stcg(yt + i, make_ulonglong2(acc[2 * i],      acc[2 * i + 1]));
        __stcg(yb + i, make_ulonglong2(acc[14 + 2 * i], acc[15 + 2 * i]));
    }
}

// ---------------------------------------------------------------------------
// Kernel 2: edge pass. out[e] = tanh(y_top[row[e]] + y_bot[col[e]])
// 256 threads / 256 edges per block. 8 lanes cooperate per edge (float4 each)
// so each gather is exactly one 128B line. ALL index arithmetic is int32
// (indices < 2^17): for int64 input only the low 32-bit word is loaded.
// ---------------------------------------------------------------------------
__global__ void __launch_bounds__(256) edge_kernel(const void* __restrict__ pA,
                                                   const void* __restrict__ pB,
                                                   float* __restrict__ out) {
    __shared__ __align__(16) float so[256 * OUT_C];  // 25600 B

    const void* ei_raw = looks_like_indices(pA) ? pA : pB;
    const int*  ei32   = (const int*)ei_raw;

    // dtype sniff: int64 indices -> every odd 32-bit word is zero.
    bool is64 = true;
#pragma unroll
    for (int i = 1; i < 64; i += 2) is64 &= (__ldg((const unsigned*)ei_raw + i) == 0u);

    const int tid  = threadIdx.x;
    const int warp = tid >> 5;
    const int lane = tid & 31;
    const int g    = lane >> 3;   // edge-within-group-of-4
    const int li   = lane & 7;    // float4 index within edge row
    const int tile = blockIdx.x * 256;

    const float* ytop = g_y;
    const float* ybot = g_y + (size_t)N_NODES * YPAD;

    // Front-batch all index loads (int32 low words; MLP = 16).
    int r[8], c[8];
    if (is64) {
#pragma unroll
        for (int it = 0; it < 8; ++it) {
            int e = tile + warp * 32 + it * 4 + g;
            r[it] = __ldcs(ei32 + 2 * e);                     // low word of int64
            c[it] = __ldcs(ei32 + 2 * (N_EDGES + e));
        }
    } else {
#pragma unroll
        for (int it = 0; it < 8; ++it) {
            int e = tile + warp * 32 + it * 4 + g;
            r[it] = __ldcs(ei32 + e);
            c[it] = __ldcs(ei32 + N_EDGES + e);
        }
    }

#pragma unroll
    for (int it = 0; it < 8; ++it) {
        int le = warp * 32 + it * 4 + g;      // local edge 0..255

        // Clamp (int32): identity on valid input; turns ABI surprises into a
        // rel_err signal instead of an illegal access.
        int ri = min(max(r[it], 0), N_NODES - 1);
        int ci = min(max(c[it], 0), N_NODES - 1);

        float4 a = __ldg((const float4*)(ytop + ri * YPAD) + li);
        float4 b = __ldg((const float4*)(ybot + ci * YPAD) + li);

        int base = le * OUT_C + li * 4;
        if (li < 6) {
            // smem addr = le*25 + li*4 + j : conflict-free across the warp
            so[base + 0] = tanh_approx(a.x + b.x);
            so[base + 1] = tanh_approx(a.y + b.y);
            so[base + 2] = tanh_approx(a.z + b.z);
            so[base + 3] = tanh_approx(a.w + b.w);
        } else if (li == 6) {
            so[base] = tanh_approx(a.x + b.x);  // element 24 only
        }
        // li == 7: load lands in the same 128B line (pad) — no extra traffic, no store
    }
    __syncthreads();

    // Coalesced streaming write: 256*25 = 6400 floats = 1600 float4 = 6*256 + 64
    const float4* so4 = (const float4*)so;
    float4* o4 = (float4*)(out + (size_t)tile * OUT_C);
#pragma unroll
    for (int i = 0; i < 6; ++i)
        __stcs(o4 + tid + i * 256, so4[tid + i * 256]);
    if (tid < 64)
        __stcs(o4 + tid + 1536, so4[tid + 1536]);
}

// ---------------------------------------------------------------------------
extern "C" void kernel_launch(void* const* d_in, const int* in_sizes, int n_in,
                              void* d_out, int out_size) {
    // W is the unique size-3200 input. x and edge_index have IDENTICAL element
    // counts (6.4M); the two are disambiguated on-device by content sniff.
    int wi = 0;
    for (int i = 0; i < n_in; ++i)
        if (in_sizes[i] == W_ELEMS) wi = i;
    int ai = (wi == 0) ? 1 : 0;
    int bi = (wi == 2) ? 1 : 2;

    const void*  pA  = d_in[ai];
    const void*  pB  = d_in[bi];
    const float* W   = (const float*)d_in[wi];
    float*       out = (float*)d_out;

    precompute_kernel<<<(N_NODES + 127) / 128, 128>>>(pA, pB, W);
    edge_kernel<<<N_EDGES / 256, 256>>>(pA, pB, out);
}